// round 1
// baseline (speedup 1.0000x reference)
#include <cuda_runtime.h>
#include <cuda_bf16.h>
#include <math.h>

// MoERouter: B=4, S=8192, D=2048. n_tokens = 32768, k = int(0.55*32768+0.5) = 18022.
//
// Pipeline (4 graph-captured launches, one stream, linear deps):
//   1) zero_hist      : clear the two 64K-bin radix histograms
//   2) gemv_kernel    : scores = H·W + b  (warp/row, float4, 256MB stream -> HBM bound)
//                       + gumbel noise -> monotone-uint key -> g_keys + hist1[key>>16]
//                       + deterministic per-block aux partials (sigmoid / s^2 / entropy)
//   3) select_kernel  : 1 block: suffix-scan hist1 -> high-16 bin B1 + residual R,
//                       build hist2 over low-16 bits within B1, suffix-scan -> exact
//                       32-bit threshold key (k-th largest). Also final deterministic
//                       aux-loss reduction -> out[32768].
//   4) mask_kernel    : out[t] = (key[t] >= T) ? 1 : 0
//
// Determinism: integer atomics only (exact); all float reductions are fixed-order
// shared-memory trees. No allocations; scratch lives in __device__ globals.

#define N_TOKENS   32768
#define DIM        2048
#define K_SEL      18022
#define GEMV_BLOCKS 4096   // 8 rows (warps) per 256-thread block

__device__ unsigned int g_keys[N_TOKENS];
__device__ int          g_hist1[65536];
__device__ int          g_hist2[65536];
__device__ float        g_part_p [GEMV_BLOCKS];
__device__ float        g_part_s2[GEMV_BLOCKS];
__device__ float        g_part_e [GEMV_BLOCKS];
__device__ unsigned int g_thresh;

// ---------------------------------------------------------------------------
__global__ void zero_hist_kernel() {
    int i = blockIdx.x * blockDim.x + threadIdx.x;   // 256*512 = 131072 threads
    if (i < 65536) g_hist1[i] = 0;
    else           g_hist2[i - 65536] = 0;
}

// ---------------------------------------------------------------------------
// monotone mapping: float -> uint preserving order (larger float -> larger uint)
__device__ __forceinline__ unsigned int float_key(float x) {
    unsigned int u = __float_as_uint(x);
    return (u & 0x80000000u) ? ~u : (u | 0x80000000u);
}

__global__ __launch_bounds__(256)
void gemv_kernel(const float* __restrict__ h,
                 const float* __restrict__ uni,
                 const float* __restrict__ W,
                 const float* __restrict__ bptr) {
    __shared__ float sW[DIM];
    __shared__ float sp[8], ss[8], se[8];

    int tid = threadIdx.x;
    for (int i = tid; i < DIM; i += 256) sW[i] = W[i];
    __syncthreads();

    int wid  = tid >> 5;
    int lane = tid & 31;
    int row  = blockIdx.x * 8 + wid;                 // 4096*8 = 32768 exactly

    const float4* hr = reinterpret_cast<const float4*>(h + (size_t)row * DIM);
    float acc = 0.0f;
    #pragma unroll
    for (int i = 0; i < 16; i++) {                   // 512 float4 per row / 32 lanes
        float4 v = __ldg(&hr[lane + 32 * i]);
        int c = (lane + 32 * i) * 4;
        acc += v.x * sW[c] + v.y * sW[c + 1] + v.z * sW[c + 2] + v.w * sW[c + 3];
    }
    #pragma unroll
    for (int o = 16; o > 0; o >>= 1)
        acc += __shfl_down_sync(0xFFFFFFFFu, acc, o);

    if (lane == 0) {
        float s = acc + bptr[0];

        // aux-loss terms (active_mask is all-ones -> plain means over all tokens)
        float p  = 1.0f / (1.0f + expf(-s));
        float pc = fminf(fmaxf(p, 1e-4f), 1.0f - 1e-4f);
        float ent = -(pc * logf(pc) + (1.0f - pc) * logf(1.0f - pc));
        sp[wid] = p; ss[wid] = s * s; se[wid] = ent;

        // gumbel noise (training path), TEMPERATURE = 1
        float u  = fminf(fmaxf(uni[row], 1e-6f), 1.0f - 1e-6f);
        float g  = fminf(fmaxf(-logf(-logf(u) + 1e-6f), -10.0f), 10.0f);
        float ns = s + g;

        unsigned int ku = float_key(ns);
        g_keys[row] = ku;
        atomicAdd(&g_hist1[ku >> 16], 1);
    }
    __syncthreads();
    if (tid == 0) {                                  // fixed-order: deterministic
        float a = 0.f, b2 = 0.f, c = 0.f;
        #pragma unroll
        for (int i = 0; i < 8; i++) { a += sp[i]; b2 += ss[i]; c += se[i]; }
        g_part_p [blockIdx.x] = a;
        g_part_s2[blockIdx.x] = b2;
        g_part_e [blockIdx.x] = c;
    }
}

// ---------------------------------------------------------------------------
__global__ __launch_bounds__(1024)
void select_kernel(float* __restrict__ out, int out_size) {
    __shared__ int   scnt[1024];
    __shared__ int   sB1, sR;
    __shared__ float sred[1024];
    __shared__ float stot[3];

    int t = threadIdx.x;
    int base = t * 64;

    // ---- pass 1: suffix-scan over hist1 (high 16 bits), find bin B1 & residual R
    int local = 0;
    #pragma unroll 8
    for (int i = 0; i < 64; i++) local += g_hist1[base + i];
    scnt[t] = local;
    __syncthreads();
    for (int off = 1; off < 1024; off <<= 1) {       // inclusive suffix sum
        int v = (t + off < 1024) ? scnt[t + off] : 0;
        __syncthreads();
        scnt[t] += v;
        __syncthreads();
    }
    int sfx = scnt[t] - local;                       // count strictly above my range
    if (sfx < K_SEL && sfx + local >= K_SEL) {
        int cum = sfx;
        for (int bin = base + 63; bin >= base; bin--) {
            int c = g_hist1[bin];
            if (cum + c >= K_SEL) { sB1 = bin; sR = K_SEL - cum; break; }
            cum += c;
        }
    }
    __syncthreads();
    int B1 = sB1, R = sR;

    // ---- build hist2 over low 16 bits within bin B1
    for (int i = t; i < N_TOKENS; i += 1024) {
        unsigned int ku = g_keys[i];
        if ((int)(ku >> 16) == B1) atomicAdd(&g_hist2[ku & 0xFFFFu], 1);
    }
    __syncthreads();                                 // same-block atomics now visible

    // ---- pass 2: suffix-scan over hist2, exact threshold key
    int local2 = 0;
    #pragma unroll 8
    for (int i = 0; i < 64; i++) local2 += g_hist2[base + i];
    scnt[t] = local2;
    __syncthreads();
    for (int off = 1; off < 1024; off <<= 1) {
        int v = (t + off < 1024) ? scnt[t + off] : 0;
        __syncthreads();
        scnt[t] += v;
        __syncthreads();
    }
    int sfx2 = scnt[t] - local2;
    if (sfx2 < R && sfx2 + local2 >= R) {
        int cum = sfx2;
        for (int bin = base + 63; bin >= base; bin--) {
            int c = g_hist2[bin];
            if (cum + c >= R) {
                g_thresh = ((unsigned int)B1 << 16) | (unsigned int)bin;
                break;
            }
            cum += c;
        }
    }

    // ---- deterministic aux-loss reduction (4096 partials, tree, fixed order)
    float a = 0.f, b2 = 0.f, c = 0.f;
    for (int i = t; i < GEMV_BLOCKS; i += 1024) {
        a  += g_part_p [i];
        b2 += g_part_s2[i];
        c  += g_part_e [i];
    }
    // three sequential shared-memory trees
    __syncthreads();
    sred[t] = a;  __syncthreads();
    for (int s = 512; s > 0; s >>= 1) { if (t < s) sred[t] += sred[t + s]; __syncthreads(); }
    if (t == 0) stot[0] = sred[0];
    __syncthreads();
    sred[t] = b2; __syncthreads();
    for (int s = 512; s > 0; s >>= 1) { if (t < s) sred[t] += sred[t + s]; __syncthreads(); }
    if (t == 0) stot[1] = sred[0];
    __syncthreads();
    sred[t] = c;  __syncthreads();
    for (int s = 512; s > 0; s >>= 1) { if (t < s) sred[t] += sred[t + s]; __syncthreads(); }
    if (t == 0) stot[2] = sred[0];
    __syncthreads();

    if (t == 0 && out_size > N_TOKENS) {
        const float Nf = (float)N_TOKENS;
        float meanp   = stot[0] / Nf;
        float lb      = (meanp - 0.55f) * (meanp - 0.55f);
        float z       = stot[1] / Nf;
        float entropy = stot[2] / Nf;
        // aux = LB_W*lb + Z_W*z + ENT_W*(-entropy)
        out[N_TOKENS] = 0.01f * lb + 1e-4f * z - 1e-3f * entropy;
    }
}

// ---------------------------------------------------------------------------
__global__ void mask_kernel(float* __restrict__ out) {
    int i = blockIdx.x * blockDim.x + threadIdx.x;
    if (i < N_TOKENS)
        out[i] = (g_keys[i] >= g_thresh) ? 1.0f : 0.0f;
}

// ---------------------------------------------------------------------------
extern "C" void kernel_launch(void* const* d_in, const int* in_sizes, int n_in,
                              void* d_out, int out_size) {
    // metadata order: hidden_states, active_mask(all-ones; unused), uniform, W, b
    // be robust to the bool mask being dropped from the input list:
    int iu = (n_in >= 5) ? 2 : 1;
    int iw = (n_in >= 5) ? 3 : 2;
    int ib = (n_in >= 5) ? 4 : 3;

    const float* h   = (const float*)d_in[0];
    const float* uni = (const float*)d_in[iu];
    const float* W   = (const float*)d_in[iw];
    const float* b   = (const float*)d_in[ib];
    float* out = (float*)d_out;

    zero_hist_kernel<<<256, 512>>>();
    gemv_kernel<<<GEMV_BLOCKS, 256>>>(h, uni, W, b);
    select_kernel<<<1, 1024>>>(out, out_size);
    mask_kernel<<<128, 256>>>(out);
}

// round 4
// speedup vs baseline: 2.0871x; 2.0871x over previous
#include <cuda_runtime.h>
#include <cuda_bf16.h>
#include <math.h>

// MoERouter: B=4, S=8192, D=2048. n_tokens = 32768, k = int(0.55*32768+0.5) = 18022.
//
// Design (2 launches):
//   1) gemv_kernel: scores = H·W + b, warp/row, float4 data AND float4 smem W
//      (conflict-free LDS.128), unroll 4 to keep regs low -> full occupancy.
//      Emits monotone-uint noisy-score keys + deterministic per-block aux partials.
//   2) select_mask_kernel (1 block, 1024 thr): exact 4-pass 8-bit radix select
//      over the 32768 keys (256-bin smem hist per pass, warp-shuffle suffix scan
//      with BLOCK-UNIFORM barriers only), deterministic aux-loss reduction, then
//      writes the 0/1 mask (float4) + aux scalar.
//
// Determinism: smem integer atomics only; all float reductions fixed-order trees.
// All __syncthreads() are executed by every thread of the block (no divergence).

#define N_TOKENS    32768
#define DIM         2048
#define K_SEL       18022
#define GEMV_BLOCKS 4096   // 8 rows (warps) per 256-thread block

__device__ unsigned int g_keys[N_TOKENS];
__device__ float        g_part_p [GEMV_BLOCKS];
__device__ float        g_part_s2[GEMV_BLOCKS];
__device__ float        g_part_e [GEMV_BLOCKS];

// monotone mapping: float -> uint preserving order (larger float -> larger uint)
__device__ __forceinline__ unsigned int float_key(float x) {
    unsigned int u = __float_as_uint(x);
    return (u & 0x80000000u) ? ~u : (u | 0x80000000u);
}

// ---------------------------------------------------------------------------
__global__ __launch_bounds__(256)
void gemv_kernel(const float* __restrict__ h,
                 const float* __restrict__ uni,
                 const float* __restrict__ W,
                 const float* __restrict__ bptr) {
    __shared__ float4 sW4[DIM / 4];               // 512 float4 = 8KB
    __shared__ float sp[8], ss[8], se[8];

    int tid = threadIdx.x;
    const float4* W4 = reinterpret_cast<const float4*>(W);
    for (int i = tid; i < DIM / 4; i += 256) sW4[i] = W4[i];
    __syncthreads();

    int wid  = tid >> 5;
    int lane = tid & 31;
    int row  = blockIdx.x * 8 + wid;              // 4096*8 = 32768 exactly

    const float4* hr = reinterpret_cast<const float4*>(h + (size_t)row * DIM);
    float acc = 0.0f;
    #pragma unroll 4
    for (int i = 0; i < 16; i++) {                // 512 float4 per row / 32 lanes
        float4 v = hr[lane + 32 * i];             // coalesced 128B/warp LDG.128
        float4 w = sW4[lane + 32 * i];            // conflict-free LDS.128
        acc = fmaf(v.x, w.x, acc);
        acc = fmaf(v.y, w.y, acc);
        acc = fmaf(v.z, w.z, acc);
        acc = fmaf(v.w, w.w, acc);
    }
    #pragma unroll
    for (int o = 16; o > 0; o >>= 1)
        acc += __shfl_down_sync(0xFFFFFFFFu, acc, o);

    if (lane == 0) {
        float s = acc + bptr[0];

        // aux-loss terms (active_mask is all-ones -> plain means over all tokens)
        float p  = 1.0f / (1.0f + expf(-s));
        float pc = fminf(fmaxf(p, 1e-4f), 1.0f - 1e-4f);
        float ent = -(pc * logf(pc) + (1.0f - pc) * logf(1.0f - pc));
        sp[wid] = p; ss[wid] = s * s; se[wid] = ent;

        // gumbel noise (training path), TEMPERATURE = 1
        float u  = fminf(fmaxf(uni[row], 1e-6f), 1.0f - 1e-6f);
        float g  = fminf(fmaxf(-logf(-logf(u) + 1e-6f), -10.0f), 10.0f);
        g_keys[row] = float_key(s + g);
    }
    __syncthreads();
    if (tid == 0) {                               // fixed order: deterministic
        float a = 0.f, b2 = 0.f, c = 0.f;
        #pragma unroll
        for (int i = 0; i < 8; i++) { a += sp[i]; b2 += ss[i]; c += se[i]; }
        g_part_p [blockIdx.x] = a;
        g_part_s2[blockIdx.x] = b2;
        g_part_e [blockIdx.x] = c;
    }
}

// ---------------------------------------------------------------------------
__global__ __launch_bounds__(1024)
void select_mask_kernel(float* __restrict__ out, int out_size) {
    __shared__ int   hist[256];
    __shared__ int   wsum[8];                      // totals of warps 0..7 (bins)
    __shared__ unsigned int sPrefix;
    __shared__ int   sR;
    __shared__ float sred[1024];
    __shared__ float stot[3];

    int t    = threadIdx.x;
    int lane = t & 31;
    int wid  = t >> 5;
    if (t == 0) { sPrefix = 0u; sR = K_SEL; }
    __syncthreads();

    const uint4* keys4 = reinterpret_cast<const uint4*>(g_keys);

    // ---- exact 4-pass radix select (descending), 8 bits per pass ----
    #pragma unroll 1
    for (int pass = 0; pass < 4; pass++) {
        int shift = 24 - 8 * pass;
        unsigned int pmask = (pass == 0) ? 0u : (0xFFFFFFFFu << (shift + 8));
        if (t < 256) hist[t] = 0;
        __syncthreads();
        unsigned int prefix = sPrefix;            // stable: written last pass, synced
        int Rcur = sR;

        for (int i = t; i < N_TOKENS / 4; i += 1024) {
            uint4 kv = keys4[i];
            if ((kv.x & pmask) == prefix) atomicAdd(&hist[(kv.x >> shift) & 0xFF], 1);
            if ((kv.y & pmask) == prefix) atomicAdd(&hist[(kv.y >> shift) & 0xFF], 1);
            if ((kv.z & pmask) == prefix) atomicAdd(&hist[(kv.z >> shift) & 0xFF], 1);
            if ((kv.w & pmask) == prefix) atomicAdd(&hist[(kv.w >> shift) & 0xFF], 1);
        }
        __syncthreads();

        // suffix sum over 256 bins. ALL 1024 threads execute this path so every
        // barrier is block-uniform; threads >= 256 carry zeros and write nothing.
        int v = (t < 256) ? hist[t] : 0;
        int s = v;
        #pragma unroll
        for (int off = 1; off < 32; off <<= 1) {   // intra-warp suffix scan
            int up = __shfl_down_sync(0xFFFFFFFFu, s, off);
            if (lane + off < 32) s += up;          // s = sum of my-bin..warp-end
        }
        if (lane == 0 && wid < 8) wsum[wid] = s;   // warp totals (32 bins each)
        __syncthreads();
        if (t < 256) {
            int hi = 0;
            #pragma unroll
            for (int w2 = 0; w2 < 8; w2++)
                if (w2 > wid) hi += wsum[w2];
            int incl  = s + hi;                    // sum hist[t..255]
            int above = incl - v;                  // count strictly above bin t
            if (incl >= Rcur && above < Rcur) {    // exactly one t matches
                sPrefix = prefix | ((unsigned int)t << shift);
                sR = Rcur - above;
            }
        }
        __syncthreads();
    }
    unsigned int T = sPrefix;                      // exact k-th largest key

    // ---- deterministic aux-loss reduction (4096 partials, fixed-order tree) ----
    float a = 0.f, b2 = 0.f, c = 0.f;
    for (int i = t; i < GEMV_BLOCKS; i += 1024) {
        a  += g_part_p [i];
        b2 += g_part_s2[i];
        c  += g_part_e [i];
    }
    sred[t] = a;  __syncthreads();
    for (int s2 = 512; s2 > 0; s2 >>= 1) { if (t < s2) sred[t] += sred[t + s2]; __syncthreads(); }
    if (t == 0) stot[0] = sred[0];
    __syncthreads();
    sred[t] = b2; __syncthreads();
    for (int s2 = 512; s2 > 0; s2 >>= 1) { if (t < s2) sred[t] += sred[t + s2]; __syncthreads(); }
    if (t == 0) stot[1] = sred[0];
    __syncthreads();
    sred[t] = c;  __syncthreads();
    for (int s2 = 512; s2 > 0; s2 >>= 1) { if (t < s2) sred[t] += sred[t + s2]; __syncthreads(); }
    if (t == 0) stot[2] = sred[0];
    __syncthreads();

    // ---- mask write (float4, keys are L2-resident) ----
    float4* out4 = reinterpret_cast<float4*>(out);
    for (int i = t; i < N_TOKENS / 4; i += 1024) {
        uint4 kv = keys4[i];
        float4 m;
        m.x = (kv.x >= T) ? 1.0f : 0.0f;
        m.y = (kv.y >= T) ? 1.0f : 0.0f;
        m.z = (kv.z >= T) ? 1.0f : 0.0f;
        m.w = (kv.w >= T) ? 1.0f : 0.0f;
        out4[i] = m;
    }

    if (t == 0 && out_size > N_TOKENS) {
        const float Nf = (float)N_TOKENS;
        float meanp   = stot[0] / Nf;
        float lb      = (meanp - 0.55f) * (meanp - 0.55f);
        float z       = stot[1] / Nf;
        float entropy = stot[2] / Nf;
        // aux = LB_W*lb + Z_W*z + ENT_W*(-entropy)
        out[N_TOKENS] = 0.01f * lb + 1e-4f * z - 1e-3f * entropy;
    }
}

// ---------------------------------------------------------------------------
extern "C" void kernel_launch(void* const* d_in, const int* in_sizes, int n_in,
                              void* d_out, int out_size) {
    // metadata order: hidden_states, active_mask(all-ones; unused), uniform, W, b
    // robust to the bool mask being dropped from the input list:
    int iu = (n_in >= 5) ? 2 : 1;
    int iw = (n_in >= 5) ? 3 : 2;
    int ib = (n_in >= 5) ? 4 : 3;

    const float* h   = (const float*)d_in[0];
    const float* uni = (const float*)d_in[iu];
    const float* W   = (const float*)d_in[iw];
    const float* b   = (const float*)d_in[ib];
    float* out = (float*)d_out;

    gemv_kernel<<<GEMV_BLOCKS, 256>>>(h, uni, W, b);
    select_mask_kernel<<<1, 1024>>>(out, out_size);
}

// round 5
// speedup vs baseline: 2.2207x; 1.0640x over previous
#include <cuda_runtime.h>
#include <cuda_bf16.h>
#include <math.h>

// MoERouter: B=4, S=8192, D=2048. n_tokens = 32768, k = int(0.55*32768+0.5) = 18022.
//
// R5 design (3 launches):
//   1) gemv_kernel: scores = H·W + b (warp/row, float4+smem-float4, DRAM-bound)
//      -> noisy-score keys + per-block aux partials
//      -> ALSO builds a global 2048-bin histogram of the top 11 key bits
//         (one spread atomicAdd per row; hidden under the 256MB stream).
//   2) select_kernel (1 block, 1024 thr): suffix-scan the 2048-bin hist -> bin B +
//      residual R; ONE sweep of the keys collects bin-B candidates (~2K) to smem;
//      remaining 21 bits refined via smem hists (11b then 10b) -> exact threshold.
//      Aux-loss reduction (shuffle trees), writes g_thresh + out[32768].
//      Re-zeroes g_hist1 for the next graph replay (globals start zeroed).
//      Exact full-radix fallback if the bin overflows CAP (block-uniform branch).
//   3) mask_kernel (32 blocks): out[t] = key[t] >= g_thresh (float4 writes).
//
// Determinism: integer atomics only; float reductions are fixed-order trees.
// Every __syncthreads() is block-uniform (branches guarded by block-uniform values).

#define N_TOKENS    32768
#define DIM         2048
#define K_SEL       18022
#define GEMV_BLOCKS 4096   // 8 rows (warps) per 256-thread block
#define CAP         8192   // candidate capacity (worst expected bin ~2K)

__device__ unsigned int g_keys[N_TOKENS];
__device__ int          g_hist1[2048];          // zero at load; select re-zeroes
__device__ float        g_part_p [GEMV_BLOCKS];
__device__ float        g_part_s2[GEMV_BLOCKS];
__device__ float        g_part_e [GEMV_BLOCKS];
__device__ unsigned int g_thresh;

// monotone mapping: float -> uint preserving order (larger float -> larger uint)
__device__ __forceinline__ unsigned int float_key(float x) {
    unsigned int u = __float_as_uint(x);
    return (u & 0x80000000u) ? ~u : (u | 0x80000000u);
}

// ---------------------------------------------------------------------------
__global__ __launch_bounds__(256)
void gemv_kernel(const float* __restrict__ h,
                 const float* __restrict__ uni,
                 const float* __restrict__ W,
                 const float* __restrict__ bptr) {
    __shared__ float4 sW4[DIM / 4];               // 8KB
    __shared__ float sp[8], ss[8], se[8];

    int tid = threadIdx.x;
    const float4* W4 = reinterpret_cast<const float4*>(W);
    for (int i = tid; i < DIM / 4; i += 256) sW4[i] = W4[i];
    __syncthreads();

    int wid  = tid >> 5;
    int lane = tid & 31;
    int row  = blockIdx.x * 8 + wid;              // 4096*8 = 32768 exactly

    const float4* hr = reinterpret_cast<const float4*>(h + (size_t)row * DIM);
    float acc = 0.0f;
    #pragma unroll 4
    for (int i = 0; i < 16; i++) {                // 512 float4 per row / 32 lanes
        float4 v = hr[lane + 32 * i];             // coalesced 128B/warp LDG.128
        float4 w = sW4[lane + 32 * i];            // conflict-free LDS.128
        acc = fmaf(v.x, w.x, acc);
        acc = fmaf(v.y, w.y, acc);
        acc = fmaf(v.z, w.z, acc);
        acc = fmaf(v.w, w.w, acc);
    }
    #pragma unroll
    for (int o = 16; o > 0; o >>= 1)
        acc += __shfl_down_sync(0xFFFFFFFFu, acc, o);

    if (lane == 0) {
        float s = acc + bptr[0];

        float p  = 1.0f / (1.0f + expf(-s));
        float pc = fminf(fmaxf(p, 1e-4f), 1.0f - 1e-4f);
        float ent = -(pc * logf(pc) + (1.0f - pc) * logf(1.0f - pc));
        sp[wid] = p; ss[wid] = s * s; se[wid] = ent;

        float u  = fminf(fmaxf(uni[row], 1e-6f), 1.0f - 1e-6f);
        float g  = fminf(fmaxf(-logf(-logf(u) + 1e-6f), -10.0f), 10.0f);
        unsigned int ku = float_key(s + g);
        g_keys[row] = ku;
        atomicAdd(&g_hist1[ku >> 21], 1);         // radix pass 1, for free
    }
    __syncthreads();
    if (tid == 0) {                               // fixed order: deterministic
        float a = 0.f, b2 = 0.f, c = 0.f;
        #pragma unroll
        for (int i = 0; i < 8; i++) { a += sp[i]; b2 += ss[i]; c += se[i]; }
        g_part_p [blockIdx.x] = a;
        g_part_s2[blockIdx.x] = b2;
        g_part_e [blockIdx.x] = c;
    }
}

// ---------------------------------------------------------------------------
__global__ __launch_bounds__(1024)
void select_kernel(float* __restrict__ out, int out_size) {
    __shared__ int          hist[2048];           // 8KB (reused for 3 levels)
    __shared__ unsigned int cand[CAP];            // 32KB candidate list
    __shared__ int          wsum[32];
    __shared__ float        sa[32], sb[32], sc[32];
    __shared__ int          sB, sR, sCnt, sNum;
    __shared__ unsigned int sT;

    int t    = threadIdx.x;
    int lane = t & 31;
    int wid  = t >> 5;

    // ---- level 0: suffix-scan global 2048-bin hist (2 bins per thread) ----
    int c0 = g_hist1[2 * t];
    int c1 = g_hist1[2 * t + 1];
    int local = c0 + c1;
    int s = local;
    #pragma unroll
    for (int off = 1; off < 32; off <<= 1) {      // intra-warp suffix scan
        int up = __shfl_down_sync(0xFFFFFFFFu, s, off);
        if (lane + off < 32) s += up;
    }
    if (lane == 0) wsum[wid] = s;
    if (t == 0) sNum = 0;
    __syncthreads();
    int hi = 0;
    #pragma unroll
    for (int w2 = 0; w2 < 32; w2++) if (w2 > wid) hi += wsum[w2];
    int incl = s + hi;                            // sum of bins [2t .. 2047]
    // bin 2t+1 (higher) wins if suffix(2t+1)>=K and suffix(2t+2)<K
    if ((incl - c0) >= K_SEL && (incl - local) < K_SEL) {
        sB = 2 * t + 1; sR = K_SEL - (incl - local); sCnt = c1;
    } else if (incl >= K_SEL && (incl - c0) < K_SEL) {
        sB = 2 * t;     sR = K_SEL - (incl - c0);    sCnt = c0;
    }
    __syncthreads();
    int B = sB, R = sR, cnt = sCnt;
    // hist1 consumed by everyone -> re-zero for next graph replay
    g_hist1[2 * t] = 0; g_hist1[2 * t + 1] = 0;

    const uint4* keys4 = reinterpret_cast<const uint4*>(g_keys);
    unsigned int T;

    if (cnt <= CAP) {                             // block-uniform branch
        // ---- single key sweep: collect bin-B candidates into smem ----
        for (int i = t; i < N_TOKENS / 4; i += 1024) {
            uint4 kv = keys4[i];
            if ((kv.x >> 21) == (unsigned)B) cand[atomicAdd(&sNum, 1)] = kv.x;
            if ((kv.y >> 21) == (unsigned)B) cand[atomicAdd(&sNum, 1)] = kv.y;
            if ((kv.z >> 21) == (unsigned)B) cand[atomicAdd(&sNum, 1)] = kv.z;
            if ((kv.w >> 21) == (unsigned)B) cand[atomicAdd(&sNum, 1)] = kv.w;
        }
        __syncthreads();
        int num = sNum;                           // == cnt

        // ---- level 1: 11-bit hist over bits [20:10] of candidates ----
        hist[2 * t] = 0; hist[2 * t + 1] = 0;
        __syncthreads();
        for (int i = t; i < num; i += 1024)
            atomicAdd(&hist[(cand[i] >> 10) & 0x7FF], 1);
        __syncthreads();
        c0 = hist[2 * t]; c1 = hist[2 * t + 1];
        local = c0 + c1; s = local;
        #pragma unroll
        for (int off = 1; off < 32; off <<= 1) {
            int up = __shfl_down_sync(0xFFFFFFFFu, s, off);
            if (lane + off < 32) s += up;
        }
        if (lane == 0) wsum[wid] = s;
        __syncthreads();
        hi = 0;
        #pragma unroll
        for (int w2 = 0; w2 < 32; w2++) if (w2 > wid) hi += wsum[w2];
        incl = s + hi;
        if ((incl - c0) >= R && (incl - local) < R) {
            sB = 2 * t + 1; sR = R - (incl - local);
        } else if (incl >= R && (incl - c0) < R) {
            sB = 2 * t;     sR = R - (incl - c0);
        }
        __syncthreads();
        int B2 = sB, R3 = sR;

        // ---- level 2: 10-bit hist over bits [9:0] (22-bit prefix match) ----
        if (t < 1024) hist[t] = 0;
        __syncthreads();
        for (int i = t; i < num; i += 1024) {
            unsigned int k = cand[i];
            if (((k >> 10) & 0x7FF) == (unsigned)B2) atomicAdd(&hist[k & 0x3FF], 1);
        }
        __syncthreads();
        c0 = hist[t];                             // 1 bin per thread (1024 bins)
        s = c0;
        #pragma unroll
        for (int off = 1; off < 32; off <<= 1) {
            int up = __shfl_down_sync(0xFFFFFFFFu, s, off);
            if (lane + off < 32) s += up;
        }
        if (lane == 0) wsum[wid] = s;
        __syncthreads();
        hi = 0;
        #pragma unroll
        for (int w2 = 0; w2 < 32; w2++) if (w2 > wid) hi += wsum[w2];
        incl = s + hi;
        if (incl >= R3 && (incl - c0) < R3)
            sT = ((unsigned)B << 21) | ((unsigned)B2 << 10) | (unsigned)t;
        __syncthreads();
        T = sT;
    } else {
        // ---- fallback: exact 4-pass 8-bit radix over all keys (rare) ----
        __shared__ unsigned int sPrefix;
        if (t == 0) { sPrefix = 0u; sR = K_SEL; }
        __syncthreads();
        #pragma unroll 1
        for (int pass = 0; pass < 4; pass++) {
            int shift = 24 - 8 * pass;
            unsigned int pmask = (pass == 0) ? 0u : (0xFFFFFFFFu << (shift + 8));
            if (t < 256) hist[t] = 0;
            __syncthreads();
            unsigned int prefix = sPrefix;
            int Rcur = sR;
            for (int i = t; i < N_TOKENS / 4; i += 1024) {
                uint4 kv = keys4[i];
                if ((kv.x & pmask) == prefix) atomicAdd(&hist[(kv.x >> shift) & 0xFF], 1);
                if ((kv.y & pmask) == prefix) atomicAdd(&hist[(kv.y >> shift) & 0xFF], 1);
                if ((kv.z & pmask) == prefix) atomicAdd(&hist[(kv.z >> shift) & 0xFF], 1);
                if ((kv.w & pmask) == prefix) atomicAdd(&hist[(kv.w >> shift) & 0xFF], 1);
            }
            __syncthreads();
            int v = (t < 256) ? hist[t] : 0;
            int s2 = v;
            #pragma unroll
            for (int off = 1; off < 32; off <<= 1) {
                int up = __shfl_down_sync(0xFFFFFFFFu, s2, off);
                if (lane + off < 32) s2 += up;
            }
            if (lane == 0 && wid < 8) wsum[wid] = s2;
            __syncthreads();
            if (t < 256) {
                int hi2 = 0;
                #pragma unroll
                for (int w2 = 0; w2 < 8; w2++) if (w2 > wid) hi2 += wsum[w2];
                int incl2  = s2 + hi2;
                int above2 = incl2 - v;
                if (incl2 >= Rcur && above2 < Rcur) {
                    sPrefix = prefix | ((unsigned)t << shift);
                    sR = Rcur - above2;
                }
            }
            __syncthreads();
        }
        T = sPrefix;
    }

    // ---- aux-loss reduction (shuffle trees, fixed order: deterministic) ----
    float a = 0.f, b2 = 0.f, c = 0.f;
    for (int i = t; i < GEMV_BLOCKS; i += 1024) {
        a  += g_part_p [i];
        b2 += g_part_s2[i];
        c  += g_part_e [i];
    }
    #pragma unroll
    for (int off = 16; off > 0; off >>= 1) {
        a  += __shfl_down_sync(0xFFFFFFFFu, a,  off);
        b2 += __shfl_down_sync(0xFFFFFFFFu, b2, off);
        c  += __shfl_down_sync(0xFFFFFFFFu, c,  off);
    }
    if (lane == 0) { sa[wid] = a; sb[wid] = b2; sc[wid] = c; }
    __syncthreads();
    if (t == 0) {
        float ta = 0.f, tb = 0.f, tc = 0.f;
        #pragma unroll
        for (int i = 0; i < 32; i++) { ta += sa[i]; tb += sb[i]; tc += sc[i]; }
        g_thresh = T;
        if (out_size > N_TOKENS) {
            const float Nf = (float)N_TOKENS;
            float meanp   = ta / Nf;
            float lb      = (meanp - 0.55f) * (meanp - 0.55f);
            float z       = tb / Nf;
            float entropy = tc / Nf;
            out[N_TOKENS] = 0.01f * lb + 1e-4f * z - 1e-3f * entropy;
        }
    }
}

// ---------------------------------------------------------------------------
__global__ __launch_bounds__(256)
void mask_kernel(float* __restrict__ out) {
    int i = blockIdx.x * blockDim.x + threadIdx.x;   // 32*256 = 8192 uint4
    unsigned int T = g_thresh;
    uint4 kv = reinterpret_cast<const uint4*>(g_keys)[i];
    float4 m;
    m.x = (kv.x >= T) ? 1.0f : 0.0f;
    m.y = (kv.y >= T) ? 1.0f : 0.0f;
    m.z = (kv.z >= T) ? 1.0f : 0.0f;
    m.w = (kv.w >= T) ? 1.0f : 0.0f;
    reinterpret_cast<float4*>(out)[i] = m;
}

// ---------------------------------------------------------------------------
extern "C" void kernel_launch(void* const* d_in, const int* in_sizes, int n_in,
                              void* d_out, int out_size) {
    // metadata order: hidden_states, active_mask(all-ones; unused), uniform, W, b
    int iu = (n_in >= 5) ? 2 : 1;
    int iw = (n_in >= 5) ? 3 : 2;
    int ib = (n_in >= 5) ? 4 : 3;

    const float* h   = (const float*)d_in[0];
    const float* uni = (const float*)d_in[iu];
    const float* W   = (const float*)d_in[iw];
    const float* b   = (const float*)d_in[ib];
    float* out = (float*)d_out;

    gemv_kernel<<<GEMV_BLOCKS, 256>>>(h, uni, W, b);
    select_kernel<<<1, 1024>>>(out, out_size);
    mask_kernel<<<32, 256>>>(out);
}